// round 11
// baseline (speedup 1.0000x reference)
#include <cuda_runtime.h>

#define IMG 224
#define NBINS 8
#define HC 28                      // cells per dim
#define FEAT (HC * HC * NBINS)     // 6272 per image
#define SROWS 16                   // pixel rows per strip
#define NSTRIPS (IMG / SROWS)      // 14
#define LROWS (SROWS + 2)          // 18 gray rows incl vertical halo
#define TSTRIDE 40                 // per-warp tile row stride (floats)
#define TSIZE (LROWS * TSTRIDE)    // 720 floats per warp tile
#define NTH 224
#define MAXB 1024

// Gaussian (SIGMA=1, CS=8) separable: g[p][c] = GY(p)*GX(c)
#define GW3 0.0021874911f          // exp(-6.125)
#define GW2 0.0439369336f          // exp(-3.125)
#define GW1 0.3246524674f          // exp(-1.125)
#define GW0 0.8824969026f          // exp(-0.125)
#define GY(p) (((p)==0||(p)==7) ? GW3 : ((p)==1||(p)==6) ? GW2 : ((p)==2||(p)==5) ? GW1 : GW0)

__device__ float        g_partial[MAXB * NSTRIPS];  // per (image, strip) sum of squares
__device__ unsigned int g_count[MAXB];              // zero-init; restored to 0 every call

__global__ void __launch_bounds__(NTH, 9)
hog_kernel(const float* __restrict__ x,
           float* __restrict__ out) {
    const int s   = blockIdx.x;     // strip
    const int b   = blockIdx.y;     // image
    const int tid = threadIdx.x;
    const int lane = tid & 31;
    const int warp = tid >> 5;      // 0..6, covers pixel cols 32*warp..32*warp+31

    __shared__ float sgray[7 * TSIZE];
    __shared__ float wsum[NTH / 32];
    __shared__ unsigned int s_arrive;
    __shared__ float s_inv;

    float* tile = sgray + warp * TSIZE;

    // ---- Warp-private gray fill (no block barrier!) ----
    // smem col sc: left halo at sc=3, cols 32w+0..35 at sc=4..39.
    const float* xb  = x + (size_t)b * 3 * IMG * IMG;
    const int    gr0 = s * SROWS - 1;
    const int    cb  = 32 * warp;          // warp's first pixel col
    {
        const int g9 = lane % 9;           // float4 group 0..8 (cols cb+4*g9..+3)
        const int r9 = lane / 9;           // 0..2 main, 3 = halo crew
        if (r9 < 3) {
            const int gc = cb + 4 * g9;
            const bool cok = (gc < IMG);   // only warp6/g9==8 is out
#pragma unroll
            for (int it = 0; it < 6; it++) {
                const int r  = r9 + 3 * it;       // 0..17
                const int gr = gr0 + r;
                float4 o = make_float4(0.f, 0.f, 0.f, 0.f);
                if (cok && (unsigned)gr < IMG) {
                    const float* base = xb + gr * IMG + gc;
                    float4 r4 = *(const float4*)(base);
                    float4 g4 = *(const float4*)(base + IMG * IMG);
                    float4 b4 = *(const float4*)(base + 2 * IMG * IMG);
                    o.x = fmaf(0.2989f, r4.x, fmaf(0.587f, g4.x, 0.114f * b4.x));
                    o.y = fmaf(0.2989f, r4.y, fmaf(0.587f, g4.y, 0.114f * b4.y));
                    o.z = fmaf(0.2989f, r4.z, fmaf(0.587f, g4.z, 0.114f * b4.z));
                    o.w = fmaf(0.2989f, r4.w, fmaf(0.587f, g4.w, 0.114f * b4.w));
                }
                *(float4*)(tile + r * TSTRIDE + 4 + 4 * g9) = o;
            }
        } else if (lane < 30) {
            // left halo column (col cb-1), rows split across 3 lanes x 6 iters
            const int gc = cb - 1;
#pragma unroll
            for (int it = 0; it < 6; it++) {
                const int r  = (lane - 27) + 3 * it;  // 0..17
                const int gr = gr0 + r;
                float v = 0.0f;
                if (gc >= 0 && (unsigned)gr < IMG) {
                    const float* base = xb + gr * IMG + gc;
                    float r0 = base[0];
                    float g0 = base[IMG * IMG];
                    float b0 = base[2 * IMG * IMG];
                    v = fmaf(0.2989f, r0, fmaf(0.587f, g0, 0.114f * b0));
                }
                tile[r * TSTRIDE + 3] = v;
            }
        }
    }
    __syncwarp();

    // ---- Compute: one thread per column, separable Sobel with rolling rows ----
    const float* col = tile + 4 + lane;

    // Column Gaussian factor (folded into reconstruct): hg = 0.5 * GX(lane&7)
    const int c7 = lane & 7;
    const int dcq = min(c7, 7 - c7);
    const float gxc = (dcq == 3) ? GW0 : (dcq == 2) ? GW1 : (dcq == 1) ? GW2 : GW3;
    const float hg = 0.5f * gxc;

    float t0, t1, d0, d1;
    {
        float a = col[-1], m = col[0], z = col[1];
        t0 = fmaf(2.0f, m, a + z);  d0 = z - a;
        a = col[TSTRIDE - 1]; m = col[TSTRIDE]; z = col[TSTRIDE + 1];
        t1 = fmaf(2.0f, m, a + z);  d1 = z - a;
    }

    float ssq = 0.0f;
    float* ob = out + (size_t)b * FEAT + s * 2 * 224;

#pragma unroll
    for (int half = 0; half < 2; half++) {
        // Quadrant-fold histogram
        float hs[4], hd[4];
#pragma unroll
        for (int k = 0; k < 4; k++) { hs[k] = 0.0f; hd[k] = 0.0f; }

#pragma unroll
        for (int p = 0; p < 8; p++) {
            const int rr = half * 8 + p + 2;
            float a = col[rr * TSTRIDE - 1];
            float m = col[rr * TSTRIDE];
            float z = col[rr * TSTRIDE + 1];
            float t2 = fmaf(2.0f, m, a + z);
            float d2 = z - a;

            float gx = fmaf(2.0f, d1, d0) + d2;
            float gy = t2 - t0;

            float s2 = fmaf(gy, gy, fmaf(gx, gx, 1e-6f));
            float mag;
            asm("sqrt.approx.f32 %0, %1;" : "=f"(mag) : "f"(s2));
            float w = mag * GY(p);

            const bool sn  = gy < 0.0f;
            float gx2 = sn ? -gx : gx;
            float sgn = sn ? -1.0f : 1.0f;
            float ay  = fabsf(gy);
            const bool pA = gx2 > 0.0f;
            const bool pD = ay < gx2;      // pD => pA
            const bool pS = ay > -gx2;     // pA => pS

            float w0 = pD         ? w : 0.0f;
            float w1 = (pA != pD) ? w : 0.0f;
            float w2 = (pA != pS) ? w : 0.0f;
            float w3 = !pS        ? w : 0.0f;
            hs[0] += w0;  hd[0] = fmaf(sgn, w0, hd[0]);
            hs[1] += w1;  hd[1] = fmaf(sgn, w1, hd[1]);
            hs[2] += w2;  hd[2] = fmaf(sgn, w2, hd[2]);
            hs[3] += w3;  hd[3] = fmaf(sgn, w3, hd[3]);

            t0 = t1; t1 = t2; d0 = d1; d1 = d2;
        }

        // Reconstruct 8 bins with column-Gaussian folded in
        float h[NBINS];
#pragma unroll
        for (int k = 0; k < 4; k++) {
            float e = hg * hs[k];
            h[k]     = fmaf( hg, hd[k], e);
            h[k + 4] = fmaf(-hg, hd[k], e);
        }

        // 8-lane multi-bin fold: within each 8-lane cell group, lane ends with bin = lane&7
        const bool q4 = (lane & 4) != 0;
        float s0 = q4 ? h[0] : h[4];
        float s1 = q4 ? h[1] : h[5];
        float s2_ = q4 ? h[2] : h[6];
        float s3 = q4 ? h[3] : h[7];
        float a0 = (q4 ? h[4] : h[0]) + __shfl_xor_sync(0xffffffffu, s0, 4);
        float a1 = (q4 ? h[5] : h[1]) + __shfl_xor_sync(0xffffffffu, s1, 4);
        float a2 = (q4 ? h[6] : h[2]) + __shfl_xor_sync(0xffffffffu, s2_, 4);
        float a3 = (q4 ? h[7] : h[3]) + __shfl_xor_sync(0xffffffffu, s3, 4);

        const bool q2 = (lane & 2) != 0;
        float u0 = q2 ? a0 : a2;
        float u1 = q2 ? a1 : a3;
        float c0 = (q2 ? a2 : a0) + __shfl_xor_sync(0xffffffffu, u0, 2);
        float c1 = (q2 ? a3 : a1) + __shfl_xor_sync(0xffffffffu, u1, 2);

        const bool q1 = (lane & 1) != 0;
        float v_ = q1 ? c0 : c1;
        float dsum = (q1 ? c1 : c0) + __shfl_xor_sync(0xffffffffu, v_, 1);

        // Coalesced: out[b][ (s*2+half)*28 + tid/8 ][ tid&7 ]
        ob[half * 224 + tid] = dsum;
        ssq = fmaf(dsum, dsum, ssq);
    }

    // Block sum of squares -> deterministic per-strip partial
#pragma unroll
    for (int o = 16; o > 0; o >>= 1)
        ssq += __shfl_xor_sync(0xffffffffu, ssq, o);
    if (lane == 0) wsum[warp] = ssq;
    __syncthreads();
    if (tid == 0) {
        float t = 0.0f;
#pragma unroll
        for (int w = 0; w < NTH / 32; w++) t += wsum[w];
        g_partial[b * NSTRIPS + s] = t;
    }

    // ---- Fused normalization: last arriving block for image b scales it ----
    __threadfence();                       // publish out rows + g_partial
    if (tid == 0) s_arrive = atomicAdd(&g_count[b], 1u);
    __syncthreads();
    if (s_arrive == NSTRIPS - 1) {
        __threadfence();                   // acquire other strips' writes
        if (tid == 0) {
            float t = 0.0f;
#pragma unroll
            for (int i = 0; i < NSTRIPS; i++) t += g_partial[b * NSTRIPS + i];
            s_inv = 1.0f / (sqrtf(t) + 1e-6f);
            g_count[b] = 0;                // restore for next launch / replay
        }
        __syncthreads();
        const float inv = s_inv;
        float4* o4 = (float4*)(out + (size_t)b * FEAT);
#pragma unroll
        for (int i = 0; i < FEAT / 4 / NTH; i++) {   // 7 iterations
            float4 v = o4[i * NTH + tid];
            v.x *= inv; v.y *= inv; v.z *= inv; v.w *= inv;
            o4[i * NTH + tid] = v;
        }
    }
}

extern "C" void kernel_launch(void* const* d_in, const int* in_sizes, int n_in,
                              void* d_out, int out_size) {
    const float* x = (const float*)d_in[0];
    float* out = (float*)d_out;

    const int bs = in_sizes[0] / (3 * IMG * IMG);

    dim3 grid(NSTRIPS, bs);
    hog_kernel<<<grid, NTH>>>(x, out);
}